// round 5
// baseline (speedup 1.0000x reference)
#include <cuda_runtime.h>
#include <math.h>

#define BB 16      // batch
#define TT 1024    // sequence
#define JJ 128     // input dim
#define HH 64      // hidden (complex) dim

// Per-(b, segment, h) local carry (complex). 16*8*64 float2 = 64 KB.
__device__ __align__(16) float2 g_C[BB * 8 * HH];

// ---------------------------------------------------------------------------
// tf32 helpers
// ---------------------------------------------------------------------------
__device__ __forceinline__ unsigned tf32bits(float v) {
    unsigned r;
    asm("cvt.rna.tf32.f32 %0, %1;" : "=r"(r) : "f"(v));
    return r;
}
__device__ __forceinline__ void mma_tf32(float& d0, float& d1, float& d2, float& d3,
                                         unsigned a0, unsigned a1, unsigned a2, unsigned a3,
                                         unsigned b0, unsigned b1) {
    asm("mma.sync.aligned.m16n8k8.row.col.f32.tf32.tf32.f32 "
        "{%0,%1,%2,%3}, {%4,%5,%6,%7}, {%8,%9}, {%0,%1,%2,%3};"
        : "+f"(d0), "+f"(d1), "+f"(d2), "+f"(d3)
        : "r"(a0), "r"(a1), "r"(a2), "r"(a3), "r"(b0), "r"(b1));
}
__device__ __forceinline__ unsigned fbits(float v) { return __float_as_uint(v); }

// ---------------------------------------------------------------------------
// K1: fused GEMM (3xTF32) + segment-local complex scan.
// Grid 128 = 16 b x 8 t-segments (128 t each). 256 threads (8 warps).
// GEMM: block tile 128t x 64h, warps 4(t) x 2(h), warp tile 32t x 32h,
//       K=128 in two 64-j chunks staged as tf32 hi/lo (stride 68, conflict-free).
// Scan: D staged [t][h] in smem; thread=(h, 32-t chunk); local scan from zero,
//       3-step serial carry combine, rerun with incoming state; y0 -> out
//       (coalesced 128B-line stores); segment carry -> g_C.
// ---------------------------------------------------------------------------
#define KST 68
#define K1_SMEM_BYTES (384 * KST * 4)   // xhi(128)+xlo(128)+bhi(64)+blo(64) rows

__global__ __launch_bounds__(256) void fused_kernel(const float* __restrict__ x,
                                                    const float* __restrict__ Bm,
                                                    const float* __restrict__ nu,
                                                    const float* __restrict__ theta,
                                                    float* __restrict__ out) {
    extern __shared__ __align__(16) float sm[];
    float* xhi = sm;                    // [t 0..127][j 0..63] stride 68
    float* xlo = sm + 128 * KST;
    float* bhi = sm + 256 * KST;        // [h 0..63][j 0..63] stride 68
    float* blo = sm + 320 * KST;

    __shared__ float Vr_s[4 * 64], Vi_s[4 * 64];
    __shared__ float Wr_s[4 * 64], Wi_s[4 * 64];

    const int tid  = threadIdx.x;
    const int lane = tid & 31;
    const int wid  = tid >> 5;
    const int wt   = wid >> 1;          // 0..3 -> 32 t
    const int wh   = wid & 1;           // 0..1 -> 32 h
    const int b    = blockIdx.x >> 3;
    const int ts   = blockIdx.x & 7;
    const int t0   = ts * 128;
    const int lr   = lane >> 2;         // 0..7
    const int lc   = lane & 3;          // 0..3

    float acc[2][4][4];
#pragma unroll
    for (int m = 0; m < 2; ++m)
#pragma unroll
        for (int n = 0; n < 4; ++n)
#pragma unroll
            for (int q = 0; q < 4; ++q) acc[m][n][q] = 0.f;

    const float4* x4 = reinterpret_cast<const float4*>(x);
    const float4* B4 = reinterpret_cast<const float4*>(Bm);

    for (int kc = 0; kc < 2; ++kc) {
        if (kc) __syncthreads();
        // Stage x chunk: 128 t x 16 float4, tf32 hi/lo split
#pragma unroll
        for (int i = 0; i < 8; ++i) {
            int f  = tid + 256 * i;
            int t  = f >> 4;
            int jq = f & 15;
            float4 v = x4[(b * TT + t0 + t) * 32 + kc * 16 + jq];
            float4 hv, lv;
            hv.x = __uint_as_float(tf32bits(v.x)); lv.x = v.x - hv.x;
            hv.y = __uint_as_float(tf32bits(v.y)); lv.y = v.y - hv.y;
            hv.z = __uint_as_float(tf32bits(v.z)); lv.z = v.z - hv.z;
            hv.w = __uint_as_float(tf32bits(v.w)); lv.w = v.w - hv.w;
            *reinterpret_cast<float4*>(&xhi[t * KST + jq * 4]) = hv;
            *reinterpret_cast<float4*>(&xlo[t * KST + jq * 4]) = lv;
        }
        // Stage B chunk: 64 h x 16 float4
#pragma unroll
        for (int i = 0; i < 4; ++i) {
            int f  = tid + 256 * i;
            int h  = f >> 4;
            int jq = f & 15;
            float4 v = B4[h * 32 + kc * 16 + jq];
            float4 hv, lv;
            hv.x = __uint_as_float(tf32bits(v.x)); lv.x = v.x - hv.x;
            hv.y = __uint_as_float(tf32bits(v.y)); lv.y = v.y - hv.y;
            hv.z = __uint_as_float(tf32bits(v.z)); lv.z = v.z - hv.z;
            hv.w = __uint_as_float(tf32bits(v.w)); lv.w = v.w - hv.w;
            *reinterpret_cast<float4*>(&bhi[h * KST + jq * 4]) = hv;
            *reinterpret_cast<float4*>(&blo[h * KST + jq * 4]) = lv;
        }
        __syncthreads();

#pragma unroll
        for (int ks = 0; ks < 8; ++ks) {
            const int j0 = ks * 8;
            unsigned ah[2][4], al[2][4];
#pragma unroll
            for (int m = 0; m < 2; ++m) {
                int base = (wt * 32 + m * 16 + lr) * KST + j0 + lc;
                ah[m][0] = fbits(xhi[base]);
                ah[m][1] = fbits(xhi[base + 8 * KST]);
                ah[m][2] = fbits(xhi[base + 4]);
                ah[m][3] = fbits(xhi[base + 8 * KST + 4]);
                al[m][0] = fbits(xlo[base]);
                al[m][1] = fbits(xlo[base + 8 * KST]);
                al[m][2] = fbits(xlo[base + 4]);
                al[m][3] = fbits(xlo[base + 8 * KST + 4]);
            }
#pragma unroll
            for (int n = 0; n < 4; ++n) {
                int hb = (wh * 32 + n * 8 + lr) * KST + j0 + lc;
                unsigned bh0 = fbits(bhi[hb]);
                unsigned bh1 = fbits(bhi[hb + 4]);
                unsigned bl0 = fbits(blo[hb]);
                unsigned bl1 = fbits(blo[hb + 4]);
#pragma unroll
                for (int m = 0; m < 2; ++m) {
                    mma_tf32(acc[m][n][0], acc[m][n][1], acc[m][n][2], acc[m][n][3],
                             ah[m][0], ah[m][1], ah[m][2], ah[m][3], bh0, bh1);
                    mma_tf32(acc[m][n][0], acc[m][n][1], acc[m][n][2], acc[m][n][3],
                             ah[m][0], ah[m][1], ah[m][2], ah[m][3], bl0, bl1);
                    mma_tf32(acc[m][n][0], acc[m][n][1], acc[m][n][2], acc[m][n][3],
                             al[m][0], al[m][1], al[m][2], al[m][3], bh0, bh1);
                }
            }
        }
    }
    __syncthreads();

    // Stage D = Bx into smem as [t][h], stride 65 (aliases staging region).
    float* sD = sm;
#pragma unroll
    for (int m = 0; m < 2; ++m)
#pragma unroll
        for (int n = 0; n < 4; ++n) {
            int tr = wt * 32 + m * 16 + lr;
            int hc = wh * 32 + n * 8 + 2 * lc;
            sD[tr * 65 + hc]           = acc[m][n][0];
            sD[tr * 65 + hc + 1]       = acc[m][n][1];
            sD[(tr + 8) * 65 + hc]     = acc[m][n][2];
            sD[(tr + 8) * 65 + hc + 1] = acc[m][n][3];
        }
    __syncthreads();

    // ---- Segment-local scan ----
    const int h = tid & 63;
    const int c = tid >> 6;             // 0..3: 32-step chunk

    const float mag = expf(-expf(nu[h]));
    float sn, cs;
    sincosf(theta[h], &sn, &cs);
    const float Lr = mag * cs;
    const float Li = mag * sn;

    float u[32];
#pragma unroll
    for (int k = 0; k < 32; ++k) u[k] = sD[(c * 32 + k) * 65 + h];

    // Phase A: local scan from zero -> chunk value V
    float yr = 0.f, yi = 0.f;
#pragma unroll
    for (int k = 0; k < 32; ++k) {
        float nyr = fmaf(Lr, yr, fmaf(-Li, yi, u[k]));
        float nyi = fmaf(Lr, yi, Li * yr);
        yr = nyr; yi = nyi;
    }
    Vr_s[c * 64 + h] = yr;
    Vi_s[c * 64 + h] = yi;
    __syncthreads();

    // Serial 4-chunk combine per h (threads 0..63), P = lam^32.
    if (tid < 64) {
        float pr = Lr, pi = Li;
#pragma unroll
        for (int s = 0; s < 5; ++s) {
            float nr = pr * pr - pi * pi;
            float ni = 2.f * pr * pi;
            pr = nr; pi = ni;
        }
        float wr = 0.f, wi = 0.f;
        Wr_s[h] = 0.f; Wi_s[h] = 0.f;
#pragma unroll
        for (int cc = 1; cc < 4; ++cc) {
            float vr = Vr_s[(cc - 1) * 64 + h];
            float vi = Vi_s[(cc - 1) * 64 + h];
            float nwr = vr + (pr * wr - pi * wi);
            float nwi = vi + (pr * wi + pi * wr);
            wr = nwr; wi = nwi;
            Wr_s[cc * 64 + h] = wr;
            Wi_s[cc * 64 + h] = wi;
        }
        float vr = Vr_s[3 * 64 + h];
        float vi = Vi_s[3 * 64 + h];
        float cr = vr + (pr * wr - pi * wi);
        float ci = vi + (pr * wi + pi * wr);
        g_C[(b * 8 + ts) * 64 + h] = make_float2(cr, ci);
    }
    __syncthreads();

    // Phase C: rerun with incoming state; coalesced stores (1 line/warp-op).
    yr = Wr_s[c * 64 + h];
    yi = Wi_s[c * 64 + h];
    float* op = out + (b * TT + t0 + c * 32) * (2 * HH) + h;
#pragma unroll
    for (int k = 0; k < 32; ++k) {
        float nyr = fmaf(Lr, yr, fmaf(-Li, yi, u[k]));
        float nyi = fmaf(Lr, yi, Li * yr);
        yr = nyr; yi = nyi;
        op[k * 128]      = yr;   // re at [b,t,h]
        op[k * 128 + 64] = yi;   // im at [b,t,H+h]
    }
}

// ---------------------------------------------------------------------------
// K2: fix-up.  out[b, t, h] += lam_h^(tl+1) * S_in(b, seg, h)
// with S_in rebuilt from the <=7 predecessor carries (parallel lookback).
// Grid 128 = (b, seg), 256 thr = 16 h-quads x 16 t-subchunks of 8.
// ---------------------------------------------------------------------------
__global__ __launch_bounds__(256) void fixup_kernel(const float* __restrict__ nu,
                                                    const float* __restrict__ theta,
                                                    float* __restrict__ out) {
    const int tid = threadIdx.x;
    const int hq  = tid & 15;           // 4 h each
    const int tc  = tid >> 4;           // 0..15, 8 steps each
    const int b   = blockIdx.x >> 3;
    const int seg = blockIdx.x & 7;
    const int h0  = hq * 4;

    float4 nv = *reinterpret_cast<const float4*>(&nu[h0]);
    float4 tv = *reinterpret_cast<const float4*>(&theta[h0]);
    float nva[4] = {nv.x, nv.y, nv.z, nv.w};
    float tva[4] = {tv.x, tv.y, tv.z, tv.w};

    float Lr[4], Li[4];
#pragma unroll
    for (int q = 0; q < 4; ++q) {
        float m = expf(-expf(nva[q]));
        float s, c;
        sincosf(tva[q], &s, &c);
        Lr[q] = m * c;
        Li[q] = m * s;
    }

    // S_in via lookback: S = 1; for g < seg: S = lam^128 * S + C_g
    float Sr[4] = {1.f, 1.f, 1.f, 1.f}, Si[4] = {0.f, 0.f, 0.f, 0.f};
    float Qr[4], Qi[4];                 // lam^128
#pragma unroll
    for (int q = 0; q < 4; ++q) {
        float pr = Lr[q], pi = Li[q];
#pragma unroll
        for (int s = 0; s < 7; ++s) {
            float nr = pr * pr - pi * pi;
            float ni = 2.f * pr * pi;
            pr = nr; pi = ni;
        }
        Qr[q] = pr; Qi[q] = pi;
    }
    for (int g = 0; g < seg; ++g) {
        const float2* cp = &g_C[(b * 8 + g) * 64 + h0];
        float4 c01 = *reinterpret_cast<const float4*>(cp);       // C[h0], C[h0+1]
        float4 c23 = *reinterpret_cast<const float4*>(cp + 2);   // C[h0+2], C[h0+3]
        float cr[4] = {c01.x, c01.z, c23.x, c23.z};
        float ci[4] = {c01.y, c01.w, c23.y, c23.w};
#pragma unroll
        for (int q = 0; q < 4; ++q) {
            float nr = Qr[q] * Sr[q] - Qi[q] * Si[q] + cr[q];
            float ni = Qr[q] * Si[q] + Qi[q] * Sr[q] + ci[q];
            Sr[q] = nr; Si[q] = ni;
        }
    }

    // z = lam^(tc*8 + 1) * S
    float zr[4], zi[4];
#pragma unroll
    for (int q = 0; q < 4; ++q) {
        // e = lam^8
        float er = Lr[q], ei = Li[q];
#pragma unroll
        for (int s = 0; s < 3; ++s) {
            float nr = er * er - ei * ei;
            float ni = 2.f * er * ei;
            er = nr; ei = ni;
        }
        // r = e^tc (tc 4 bits)
        float rr = 1.f, ri = 0.f;
        float pr = er, pi = ei;
#pragma unroll
        for (int d = 0; d < 4; ++d) {
            if ((tc >> d) & 1) {
                float nr = rr * pr - ri * pi;
                float ni = rr * pi + ri * pr;
                rr = nr; ri = ni;
            }
            float nr2 = pr * pr - pi * pi;
            float ni2 = 2.f * pr * pi;
            pr = nr2; pi = ni2;
        }
        // z = lam * r * S
        float ar = Lr[q] * rr - Li[q] * ri;
        float ai = Lr[q] * ri + Li[q] * rr;
        zr[q] = ar * Sr[q] - ai * Si[q];
        zi[q] = ar * Si[q] + ai * Sr[q];
    }

    float* p = out + (b * TT + seg * 128 + tc * 8) * (2 * HH) + h0;
#pragma unroll
    for (int k = 0; k < 8; ++k) {
        float4 re = *reinterpret_cast<float4*>(p + k * 128);
        float4 im = *reinterpret_cast<float4*>(p + k * 128 + 64);
        re.x += zr[0]; re.y += zr[1]; re.z += zr[2]; re.w += zr[3];
        im.x += zi[0]; im.y += zi[1]; im.z += zi[2]; im.w += zi[3];
        *reinterpret_cast<float4*>(p + k * 128)      = re;
        *reinterpret_cast<float4*>(p + k * 128 + 64) = im;
#pragma unroll
        for (int q = 0; q < 4; ++q) {
            float nr = Lr[q] * zr[q] - Li[q] * zi[q];
            float ni = Lr[q] * zi[q] + Li[q] * zr[q];
            zr[q] = nr; zi[q] = ni;
        }
    }
}

// ---------------------------------------------------------------------------
extern "C" void kernel_launch(void* const* d_in, const int* in_sizes, int n_in,
                              void* d_out, int out_size) {
    const float* x     = (const float*)d_in[0];   // [16,1024,128]
    const float* Bm    = (const float*)d_in[1];   // [64,128]
    const float* nu    = (const float*)d_in[2];   // [64]
    const float* theta = (const float*)d_in[3];   // [64]
    float* out = (float*)d_out;                   // [16,1024,128]

    cudaFuncSetAttribute(fused_kernel,
                         cudaFuncAttributeMaxDynamicSharedMemorySize,
                         K1_SMEM_BYTES);
    fused_kernel<<<128, 256, K1_SMEM_BYTES>>>(x, Bm, nu, theta, out);
    fixup_kernel<<<128, 256>>>(nu, theta, out);
}